// round 6
// baseline (speedup 1.0000x reference)
#include <cuda_runtime.h>
#include <cuda_bf16.h>
#include <math.h>

// inputs: x[f32] (unused), src[i32 E], dst[i32 E], path_len[i32 E], b[f32 5].
// output: f32 N*N.  out = zeros; out[src[i],dst[i]] = b[min(plen[i],5)-1],
// LAST duplicate wins.
//
// NaN-space keys (KEY_BASE=0x7F800001): as signed ints, keys exceed every
// finite float bit pattern and the 0xAA poison, so atomicMax/red.max needs no
// zeroed baseline.
//
// Persistent dirty map (1 byte per int4 group of the matrix): the graph
// replays identical work, so the dirty set is identical every call — bits only
// ever re-assert the same truth; no clearing needed. Decode writes zeros to
// clean groups WITHOUT reading the matrix (mandatory: call 1 starts from
// poison), and decodes only dirty groups.
//
//   Pass A: red.max(out_i[pos], KEY_BASE+i); g_vals[i]=b[..]; g_dirty[pos>>2]=1
//   Pass B: clean group  -> store 16B zeros (dense, coalesced)
//           dirty group  -> read 4 cells; key -> g_vals[key-BASE], else 0

#ifndef MAX_PATH_DISTANCE
#define MAX_PATH_DISTANCE 5
#endif

#define KEY_BASE 0x7F800001
#define E_MAX (4 * 1024 * 1024)
#define NGROUPS_MAX (16 * 1024 * 1024)   // (8192*8192)/4

__device__ float g_vals[E_MAX];
__device__ unsigned char g_dirty[NGROUPS_MAX];

__device__ __forceinline__ void red_max(int* p, int v) {
    asm volatile("red.global.max.s32 [%0], %1;" :: "l"(p), "r"(v) : "memory");
}

// ---------------- Pass A: scatter + vals + dirty ----------------
__global__ void scatter_kernel(const int* __restrict__ src,
                               const int* __restrict__ dst,
                               const int* __restrict__ plen,
                               const float* __restrict__ b,
                               int* __restrict__ out_i,
                               int n_pairs, int n_nodes) {
    int t = blockIdx.x * blockDim.x + threadIdx.x;
    int base = t * 8;
    if (base >= n_pairs) return;

    if (base + 7 < n_pairs) {
        int4 s0 = *reinterpret_cast<const int4*>(src + base);
        int4 s1 = *reinterpret_cast<const int4*>(src + base + 4);
        int4 d0 = *reinterpret_cast<const int4*>(dst + base);
        int4 d1 = *reinterpret_cast<const int4*>(dst + base + 4);
        int4 p0 = *reinterpret_cast<const int4*>(plen + base);
        int4 p1 = *reinterpret_cast<const int4*>(plen + base + 4);

        long long q0 = (long long)s0.x * n_nodes + d0.x;
        long long q1 = (long long)s0.y * n_nodes + d0.y;
        long long q2 = (long long)s0.z * n_nodes + d0.z;
        long long q3 = (long long)s0.w * n_nodes + d0.w;
        long long q4 = (long long)s1.x * n_nodes + d1.x;
        long long q5 = (long long)s1.y * n_nodes + d1.y;
        long long q6 = (long long)s1.z * n_nodes + d1.z;
        long long q7 = (long long)s1.w * n_nodes + d1.w;

        red_max(out_i + q0, KEY_BASE + base + 0);
        red_max(out_i + q1, KEY_BASE + base + 1);
        red_max(out_i + q2, KEY_BASE + base + 2);
        red_max(out_i + q3, KEY_BASE + base + 3);
        red_max(out_i + q4, KEY_BASE + base + 4);
        red_max(out_i + q5, KEY_BASE + base + 5);
        red_max(out_i + q6, KEY_BASE + base + 6);
        red_max(out_i + q7, KEY_BASE + base + 7);

        g_dirty[q0 >> 2] = 1; g_dirty[q1 >> 2] = 1;
        g_dirty[q2 >> 2] = 1; g_dirty[q3 >> 2] = 1;
        g_dirty[q4 >> 2] = 1; g_dirty[q5 >> 2] = 1;
        g_dirty[q6 >> 2] = 1; g_dirty[q7 >> 2] = 1;

        float4 v0, v1;
        v0.x = __ldg(&b[min(p0.x, MAX_PATH_DISTANCE) - 1]);
        v0.y = __ldg(&b[min(p0.y, MAX_PATH_DISTANCE) - 1]);
        v0.z = __ldg(&b[min(p0.z, MAX_PATH_DISTANCE) - 1]);
        v0.w = __ldg(&b[min(p0.w, MAX_PATH_DISTANCE) - 1]);
        v1.x = __ldg(&b[min(p1.x, MAX_PATH_DISTANCE) - 1]);
        v1.y = __ldg(&b[min(p1.y, MAX_PATH_DISTANCE) - 1]);
        v1.z = __ldg(&b[min(p1.z, MAX_PATH_DISTANCE) - 1]);
        v1.w = __ldg(&b[min(p1.w, MAX_PATH_DISTANCE) - 1]);
        *reinterpret_cast<float4*>(g_vals + base)     = v0;
        *reinterpret_cast<float4*>(g_vals + base + 4) = v1;
    } else {
        for (int k = base; k < n_pairs; ++k) {
            long long pos = (long long)src[k] * n_nodes + dst[k];
            red_max(out_i + pos, KEY_BASE + k);
            g_dirty[pos >> 2] = 1;
            g_vals[k] = __ldg(&b[min(plen[k], MAX_PATH_DISTANCE) - 1]);
        }
    }
}

// ---------------- Pass B: zero-fill + decode dirty groups ----------------
__global__ void decode_kernel(int* __restrict__ out_i, int ngroups) {
    int g = blockIdx.x * blockDim.x + threadIdx.x;   // one int4 group per thread
    if (g >= ngroups) return;

    float4 r = make_float4(0.f, 0.f, 0.f, 0.f);
    if (g_dirty[g]) {
        int4 v = *reinterpret_cast<const int4*>(out_i + g * 4);
        if (v.x >= KEY_BASE) r.x = __ldg(&g_vals[v.x - KEY_BASE]);
        if (v.y >= KEY_BASE) r.y = __ldg(&g_vals[v.y - KEY_BASE]);
        if (v.z >= KEY_BASE) r.z = __ldg(&g_vals[v.z - KEY_BASE]);
        if (v.w >= KEY_BASE) r.w = __ldg(&g_vals[v.w - KEY_BASE]);
    }
    *reinterpret_cast<float4*>(out_i + g * 4) = r;   // dense coalesced store
}

extern "C" void kernel_launch(void* const* d_in, const int* in_sizes, int n_in,
                              void* d_out, int out_size) {
    const int* src  = (const int*)d_in[1];
    const int* dst  = (const int*)d_in[2];
    const int* plen = (const int*)d_in[3];
    const float* b  = (const float*)d_in[4];

    int n_pairs = in_sizes[1];
    int n_nodes = (int)llround(sqrt((double)out_size));
    int* out_i = (int*)d_out;

    // Pass A
    {
        int threads = 256;
        int work = (n_pairs + 7) / 8;
        int blocks = (work + threads - 1) / threads;
        scatter_kernel<<<blocks, threads>>>(src, dst, plen, b, out_i,
                                            n_pairs, n_nodes);
    }

    // Pass B
    {
        int ngroups = out_size / 4;
        int threads = 256;
        int blocks = (ngroups + threads - 1) / threads;
        decode_kernel<<<blocks, threads>>>(out_i, ngroups);
    }
}

// round 7
// speedup vs baseline: 1.3445x; 1.3445x over previous
#include <cuda_runtime.h>
#include <cuda_bf16.h>
#include <math.h>

// inputs: x[f32] (unused), src[i32 E], dst[i32 E], path_len[i32 E], b[f32 5].
// output: f32 N*N.  out = zeros; out[src[i],dst[i]] = b[min(plen[i],5)-1],
// LAST duplicate (highest i) winning.
//
// Row-binning architecture (no atomics on the output matrix):
//   Z: zero per-row counters
//   H: histogram pairs by src row (L2-resident counters)
//   S: exclusive scan -> g_start
//   B: scatter pairs into row bins: int2{ key=(i+1)<<3 | idx, dst }
//      slot = atomicAdd(g_start[src]); afterwards g_start[r] = begin of row r+1
//   A: one CTA per row: smem tile zeroed, atomicMax(smem[dst], key) resolves
//      last-write-wins (key monotone in i), then dense coalesced row store:
//      key ? b[key&7] : 0.  Matrix written exactly once, streaming.

#ifndef MAX_PATH_DISTANCE
#define MAX_PATH_DISTANCE 5
#endif

#define N_MAX 8192
#define E_MAX (4 * 1024 * 1024)

__device__ int  g_count[N_MAX];
__device__ int  g_start[N_MAX];
__device__ int2 g_bins[E_MAX];

// ---------------- Z: zero counters ----------------
__global__ void zero_kernel(int n) {
    int t = blockIdx.x * blockDim.x + threadIdx.x;
    if (t < n) g_count[t] = 0;
}

// ---------------- H: histogram by src ----------------
__global__ void hist_kernel(const int* __restrict__ src, int n_pairs) {
    int t = blockIdx.x * blockDim.x + threadIdx.x;
    int base = t * 8;
    if (base >= n_pairs) return;
    if (base + 7 < n_pairs) {
        int4 s0 = *reinterpret_cast<const int4*>(src + base);
        int4 s1 = *reinterpret_cast<const int4*>(src + base + 4);
        atomicAdd(&g_count[s0.x], 1); atomicAdd(&g_count[s0.y], 1);
        atomicAdd(&g_count[s0.z], 1); atomicAdd(&g_count[s0.w], 1);
        atomicAdd(&g_count[s1.x], 1); atomicAdd(&g_count[s1.y], 1);
        atomicAdd(&g_count[s1.z], 1); atomicAdd(&g_count[s1.w], 1);
    } else {
        for (int k = base; k < n_pairs; ++k) atomicAdd(&g_count[src[k]], 1);
    }
}

// ---------------- S: exclusive scan (single CTA, 1024 thr x 8) ----------------
__global__ void scan_kernel(int n) {
    __shared__ int sdata[1024];
    int t = threadIdx.x;
    int vals[8];
    int sum = 0;
#pragma unroll
    for (int j = 0; j < 8; ++j) {
        int i = t * 8 + j;
        vals[j] = (i < n) ? g_count[i] : 0;
        sum += vals[j];
    }
    sdata[t] = sum;
    __syncthreads();
    // Hillis-Steele inclusive scan over thread sums
    for (int off = 1; off < 1024; off <<= 1) {
        int v = (t >= off) ? sdata[t - off] : 0;
        __syncthreads();
        sdata[t] += v;
        __syncthreads();
    }
    int run = sdata[t] - sum;   // exclusive prefix for this thread
#pragma unroll
    for (int j = 0; j < 8; ++j) {
        int i = t * 8 + j;
        if (i < n) g_start[i] = run;
        run += vals[j];
    }
}

// ---------------- B: bin pairs by src row ----------------
__global__ void bin_kernel(const int* __restrict__ src,
                           const int* __restrict__ dst,
                           const int* __restrict__ plen,
                           int n_pairs) {
    int t = blockIdx.x * blockDim.x + threadIdx.x;
    int base = t * 8;
    if (base >= n_pairs) return;

    if (base + 7 < n_pairs) {
        int4 s0 = *reinterpret_cast<const int4*>(src + base);
        int4 s1 = *reinterpret_cast<const int4*>(src + base + 4);
        int4 d0 = *reinterpret_cast<const int4*>(dst + base);
        int4 d1 = *reinterpret_cast<const int4*>(dst + base + 4);
        int4 p0 = *reinterpret_cast<const int4*>(plen + base);
        int4 p1 = *reinterpret_cast<const int4*>(plen + base + 4);

        int s[8] = {s0.x, s0.y, s0.z, s0.w, s1.x, s1.y, s1.z, s1.w};
        int d[8] = {d0.x, d0.y, d0.z, d0.w, d1.x, d1.y, d1.z, d1.w};
        int p[8] = {p0.x, p0.y, p0.z, p0.w, p1.x, p1.y, p1.z, p1.w};
#pragma unroll
        for (int j = 0; j < 8; ++j) {
            int idx = min(p[j], MAX_PATH_DISTANCE) - 1;          // 0..4
            int key = ((base + j + 1) << 3) | idx;               // >0, <2^26
            int slot = atomicAdd(&g_start[s[j]], 1);
            g_bins[slot] = make_int2(key, d[j]);
        }
    } else {
        for (int k = base; k < n_pairs; ++k) {
            int idx = min(plen[k], MAX_PATH_DISTANCE) - 1;
            int key = ((k + 1) << 3) | idx;
            int slot = atomicAdd(&g_start[src[k]], 1);
            g_bins[slot] = make_int2(key, dst[k]);
        }
    }
}

// ---------------- A: per-row resolve + dense write ----------------
__global__ void apply_kernel(float* __restrict__ out,
                             const float* __restrict__ b,
                             int n_nodes) {
    __shared__ int row[N_MAX];
    __shared__ float bs[8];

    int r = blockIdx.x;
    int t = threadIdx.x;
    int nt = blockDim.x;

    // zero the row tile (vectorized)
    int n4 = n_nodes >> 2;
    int4 z4 = make_int4(0, 0, 0, 0);
    for (int i = t; i < n4; i += nt)
        reinterpret_cast<int4*>(row)[i] = z4;
    if (t < 8) bs[t] = b[min(t, MAX_PATH_DISTANCE - 1)];
    __syncthreads();

    // post-binning: g_start[r] = begin of row r+1; begin of row r = g_start[r-1]
    int begin = (r == 0) ? 0 : g_start[r - 1];
    int end   = g_start[r];

    for (int i = begin + t; i < end; i += nt) {
        int2 e = g_bins[i];
        atomicMax(&row[e.y], e.x);
    }
    __syncthreads();

    // dense coalesced row store
    float* orow = out + (size_t)r * n_nodes;
    for (int i = t; i < n4; i += nt) {
        int4 v = reinterpret_cast<const int4*>(row)[i];
        float4 o;
        o.x = v.x ? bs[v.x & 7] : 0.0f;
        o.y = v.y ? bs[v.y & 7] : 0.0f;
        o.z = v.z ? bs[v.z & 7] : 0.0f;
        o.w = v.w ? bs[v.w & 7] : 0.0f;
        reinterpret_cast<float4*>(orow)[i] = o;
    }
}

extern "C" void kernel_launch(void* const* d_in, const int* in_sizes, int n_in,
                              void* d_out, int out_size) {
    const int* src  = (const int*)d_in[1];
    const int* dst  = (const int*)d_in[2];
    const int* plen = (const int*)d_in[3];
    const float* b  = (const float*)d_in[4];

    int n_pairs = in_sizes[1];
    int n_nodes = (int)llround(sqrt((double)out_size));
    float* out = (float*)d_out;

    // Z: zero counters
    zero_kernel<<<(n_nodes + 255) / 256, 256>>>(n_nodes);

    // H: histogram
    {
        int work = (n_pairs + 7) / 8;
        hist_kernel<<<(work + 255) / 256, 256>>>(src, n_pairs);
    }

    // S: exclusive scan -> g_start
    scan_kernel<<<1, 1024>>>(n_nodes);

    // B: bin pairs
    {
        int work = (n_pairs + 7) / 8;
        bin_kernel<<<(work + 255) / 256, 256>>>(src, dst, plen, n_pairs);
    }

    // A: per-row resolve + dense write
    apply_kernel<<<n_nodes, 256>>>(out, b, n_nodes);
}

// round 8
// speedup vs baseline: 1.8940x; 1.4087x over previous
#include <cuda_runtime.h>
#include <cuda_bf16.h>
#include <math.h>

// inputs: x[f32] (unused), src[i32 E], dst[i32 E], path_len[i32 E], b[f32 5].
// output: f32 N*N.  out = zeros; out[src[i],dst[i]] = b[min(plen[i],5)-1],
// LAST duplicate (highest i) wins.
//
// Multisplit row-binning (NO global atomics anywhere):
//   H2 : per-CTA smem histogram of src over its pair chunk -> g_cnt[cta][row]
//   S2a: per-row totals across CTAs (coalesced)
//   SC : exclusive scan of totals -> g_rowStart
//   S2c: g_cnt[cta][row] -> absolute start offset (in-place, coalesced)
//   B2 : per-CTA smem cursors; slot = smem atomicAdd -> g_bins[slot]={key,dst}
//   AP : one CTA per row: smem atomicMax(tile[dst], key) resolves last-wins
//        (key monotone in pair index), dense coalesced row store.

#ifndef MAX_PATH_DISTANCE
#define MAX_PATH_DISTANCE 5
#endif

#define N_MAX 8192
#define E_MAX (4 * 1024 * 1024)
#define NCTA  256

__device__ int  g_cnt[NCTA * N_MAX];   // per-(cta,row) counts -> offsets (8 MB)
__device__ int  g_total[N_MAX];
__device__ int  g_rowStart[N_MAX];
__device__ int2 g_bins[E_MAX];         // 32 MB

// ---------------- H2: per-CTA smem histogram ----------------
__global__ void hist2_kernel(const int* __restrict__ src, int n_pairs, int chunk) {
    __shared__ int cnt[N_MAX];
    int t = threadIdx.x, nt = blockDim.x, c = blockIdx.x;
    for (int i = t; i < N_MAX; i += nt) cnt[i] = 0;
    __syncthreads();

    int begin = c * chunk;                       // chunk is a multiple of 4
    int end = min(begin + chunk, n_pairs);
    int nfull = begin + ((end - begin) & ~3);

    for (int base = begin + t * 4; base + 3 < nfull + 4 && base + 3 < end + 4; ) break;
    for (int base = begin + t * 4; base < nfull; base += nt * 4) {
        int4 s = *reinterpret_cast<const int4*>(src + base);
        atomicAdd(&cnt[s.x], 1); atomicAdd(&cnt[s.y], 1);
        atomicAdd(&cnt[s.z], 1); atomicAdd(&cnt[s.w], 1);
    }
    for (int k = nfull + t; k < end; k += nt) atomicAdd(&cnt[src[k]], 1);
    __syncthreads();

    for (int i = t; i < N_MAX; i += nt)
        g_cnt[c * N_MAX + i] = cnt[i];           // coalesced
}

// ---------------- S2a: per-row totals ----------------
__global__ void rowsum_kernel() {
    int r = blockIdx.x * blockDim.x + threadIdx.x;
    if (r >= N_MAX) return;
    int sum = 0;
#pragma unroll 8
    for (int c = 0; c < NCTA; ++c) sum += g_cnt[c * N_MAX + r];   // coalesced
    g_total[r] = sum;
}

// ---------------- SC: exclusive scan of totals ----------------
__global__ void scan_kernel(int n) {
    __shared__ int sdata[1024];
    int t = threadIdx.x;
    int vals[8];
    int sum = 0;
#pragma unroll
    for (int j = 0; j < 8; ++j) {
        int i = t * 8 + j;
        vals[j] = (i < n) ? g_total[i] : 0;
        sum += vals[j];
    }
    sdata[t] = sum;
    __syncthreads();
    for (int off = 1; off < 1024; off <<= 1) {
        int v = (t >= off) ? sdata[t - off] : 0;
        __syncthreads();
        sdata[t] += v;
        __syncthreads();
    }
    int run = sdata[t] - sum;
#pragma unroll
    for (int j = 0; j < 8; ++j) {
        int i = t * 8 + j;
        if (i < n) g_rowStart[i] = run;
        run += vals[j];
    }
}

// ---------------- S2c: counts -> absolute offsets (in place) ----------------
__global__ void offsets_kernel() {
    int r = blockIdx.x * blockDim.x + threadIdx.x;
    if (r >= N_MAX) return;
    int run = g_rowStart[r];
#pragma unroll 8
    for (int c = 0; c < NCTA; ++c) {
        int tmp = g_cnt[c * N_MAX + r];
        g_cnt[c * N_MAX + r] = run;              // coalesced
        run += tmp;
    }
}

// ---------------- B2: place pairs via smem cursors ----------------
__global__ void bin2_kernel(const int* __restrict__ src,
                            const int* __restrict__ dst,
                            const int* __restrict__ plen,
                            int n_pairs, int chunk) {
    __shared__ int cur[N_MAX];
    int t = threadIdx.x, nt = blockDim.x, c = blockIdx.x;
    for (int i = t; i < N_MAX; i += nt) cur[i] = g_cnt[c * N_MAX + i];
    __syncthreads();

    int begin = c * chunk;
    int end = min(begin + chunk, n_pairs);
    int nfull = begin + ((end - begin) & ~3);

    for (int base = begin + t * 4; base < nfull; base += nt * 4) {
        int4 s = *reinterpret_cast<const int4*>(src + base);
        int4 d = *reinterpret_cast<const int4*>(dst + base);
        int4 p = *reinterpret_cast<const int4*>(plen + base);
        int ss[4] = {s.x, s.y, s.z, s.w};
        int dd[4] = {d.x, d.y, d.z, d.w};
        int pp[4] = {p.x, p.y, p.z, p.w};
#pragma unroll
        for (int j = 0; j < 4; ++j) {
            int idx = min(pp[j], MAX_PATH_DISTANCE) - 1;     // 0..4
            int key = ((base + j + 1) << 3) | idx;           // >0, monotone in i
            int slot = atomicAdd(&cur[ss[j]], 1);
            g_bins[slot] = make_int2(key, dd[j]);
        }
    }
    for (int k = nfull + t; k < end; k += nt) {
        int idx = min(plen[k], MAX_PATH_DISTANCE) - 1;
        int key = ((k + 1) << 3) | idx;
        int slot = atomicAdd(&cur[src[k]], 1);
        g_bins[slot] = make_int2(key, dst[k]);
    }
}

// ---------------- AP: per-row resolve + dense write ----------------
__global__ void apply_kernel(float* __restrict__ out,
                             const float* __restrict__ b,
                             int n_nodes) {
    __shared__ int row[N_MAX];
    __shared__ float bs[8];

    int r = blockIdx.x;
    int t = threadIdx.x;
    int nt = blockDim.x;

    int n4 = n_nodes >> 2;
    int4 z4 = make_int4(0, 0, 0, 0);
    for (int i = t; i < n4; i += nt)
        reinterpret_cast<int4*>(row)[i] = z4;
    if (t < 8) bs[t] = b[min(t, MAX_PATH_DISTANCE - 1)];
    __syncthreads();

    int begin = g_rowStart[r];
    int end   = begin + g_total[r];

    for (int i = begin + t; i < end; i += nt) {
        int2 e = g_bins[i];                      // coalesced segment read
        atomicMax(&row[e.y], e.x);               // spread smem atomics
    }
    __syncthreads();

    float* orow = out + (size_t)r * n_nodes;
    for (int i = t; i < n4; i += nt) {
        int4 v = reinterpret_cast<const int4*>(row)[i];
        float4 o;
        o.x = v.x ? bs[v.x & 7] : 0.0f;
        o.y = v.y ? bs[v.y & 7] : 0.0f;
        o.z = v.z ? bs[v.z & 7] : 0.0f;
        o.w = v.w ? bs[v.w & 7] : 0.0f;
        reinterpret_cast<float4*>(orow)[i] = o;
    }
}

extern "C" void kernel_launch(void* const* d_in, const int* in_sizes, int n_in,
                              void* d_out, int out_size) {
    const int* src  = (const int*)d_in[1];
    const int* dst  = (const int*)d_in[2];
    const int* plen = (const int*)d_in[3];
    const float* b  = (const float*)d_in[4];

    int n_pairs = in_sizes[1];
    int n_nodes = (int)llround(sqrt((double)out_size));
    float* out = (float*)d_out;

    int chunk = (n_pairs + NCTA - 1) / NCTA;
    chunk = (chunk + 3) & ~3;                    // 4-aligned chunks for int4

    hist2_kernel<<<NCTA, 256>>>(src, n_pairs, chunk);
    rowsum_kernel<<<N_MAX / 256, 256>>>();
    scan_kernel<<<1, 1024>>>(n_nodes);
    offsets_kernel<<<N_MAX / 256, 256>>>();
    bin2_kernel<<<NCTA, 256>>>(src, dst, plen, n_pairs, chunk);
    apply_kernel<<<n_nodes, 256>>>(out, b, n_nodes);
}